// round 1
// baseline (speedup 1.0000x reference)
#include <cuda_runtime.h>

#define N_TOK 2304
#define DIMX 384
#define NHEADS 8
#define KD 32
#define DV 128
#define DH 1024
#define SCALE_F 0.17677669529663687f

// Scratch (allocation-free rule: __device__ globals)
__device__ float g_Q[NHEADS * N_TOK * KD];   // [h][n][32]
__device__ float g_K[NHEADS * N_TOK * KD];   // [h][n][32]
__device__ float g_V[NHEADS * N_TOK * DV];   // [h][n][128]
__device__ float g_O[N_TOK * DH];            // [n][h*128+d]

// ---------------------------------------------------------------------------
// Kernel 1: fused QKV projection.  C = x @ W^T + b  (2304 x 1536), scattered
// into per-head Q/K/V layouts. 64x64 tile, BK=16, 256 threads, 4x4 per thread.
// ---------------------------------------------------------------------------
__global__ __launch_bounds__(256) void qkv_kernel(
    const float* __restrict__ x,
    const float* __restrict__ q_w, const float* __restrict__ q_b,
    const float* __restrict__ k_w, const float* __restrict__ k_b,
    const float* __restrict__ v_w, const float* __restrict__ v_b)
{
    __shared__ float sA[16][64];
    __shared__ float sB[16][64];

    const int tid = threadIdx.x;
    const int ty = tid >> 4, tx = tid & 15;
    const int rowBase = blockIdx.x * 64;
    const int colBase = blockIdx.y * 64;

    const float* W; const float* bias; int sel, wBase;
    if (colBase < 256)      { W = q_w; bias = q_b; sel = 0; wBase = colBase;       }
    else if (colBase < 512) { W = k_w; bias = k_b; sel = 1; wBase = colBase - 256; }
    else                    { W = v_w; bias = v_b; sel = 2; wBase = colBase - 512; }

    float acc[4][4];
    #pragma unroll
    for (int i = 0; i < 4; i++)
        #pragma unroll
        for (int j = 0; j < 4; j++) acc[i][j] = 0.f;

    const int lr = tid >> 2;         // 0..63 row within tile
    const int lk = (tid & 3) << 2;   // 0,4,8,12

    for (int k0 = 0; k0 < DIMX; k0 += 16) {
        float4 a = *(const float4*)(x + (rowBase + lr) * DIMX + k0 + lk);
        sA[lk + 0][lr] = a.x; sA[lk + 1][lr] = a.y;
        sA[lk + 2][lr] = a.z; sA[lk + 3][lr] = a.w;
        float4 b = *(const float4*)(W + (wBase + lr) * DIMX + k0 + lk);
        sB[lk + 0][lr] = b.x; sB[lk + 1][lr] = b.y;
        sB[lk + 2][lr] = b.z; sB[lk + 3][lr] = b.w;
        __syncthreads();
        #pragma unroll
        for (int kk = 0; kk < 16; kk++) {
            float4 ra = *(const float4*)&sA[kk][ty * 4];
            float4 rb = *(const float4*)&sB[kk][tx * 4];
            float av[4] = {ra.x, ra.y, ra.z, ra.w};
            float bv[4] = {rb.x, rb.y, rb.z, rb.w};
            #pragma unroll
            for (int i = 0; i < 4; i++)
                #pragma unroll
                for (int j = 0; j < 4; j++) acc[i][j] += av[i] * bv[j];
        }
        __syncthreads();
    }

    #pragma unroll
    for (int i = 0; i < 4; i++) {
        int n = rowBase + ty * 4 + i;
        #pragma unroll
        for (int j = 0; j < 4; j++) {
            int jl = wBase + tx * 4 + j;
            float val = acc[i][j] + bias[jl];
            if (sel == 0)
                g_Q[((jl >> 5) * N_TOK + n) * KD + (jl & 31)] = val;
            else if (sel == 1)
                g_K[((jl >> 5) * N_TOK + n) * KD + (jl & 31)] = val;
            else
                g_V[((jl >> 7) * N_TOK + n) * DV + (jl & 127)] = val;
        }
    }
}

// ---------------------------------------------------------------------------
// Kernel 2: flash-style attention per (q-tile, head).
// BQ=128 query rows, BK=64 keys/iter, 256 threads.
// Bias row for this head cached in smem; gather index loaded from gmem.
// ---------------------------------------------------------------------------
#define SQ_OFF   0                       // 128*32      = 4096 floats
#define SK_OFF   (SQ_OFF + 128 * 32)     // 64*33       = 2112
#define SV_OFF   (SK_OFF + 64 * 33)      // 64*132      = 8448
#define SS_OFF   (SV_OFF + 64 * 132)     // 128*65      = 8320
#define SBIAS_OFF (SS_OFF + 128 * 65)    // 2304
#define SALPHA_OFF (SBIAS_OFF + N_TOK)   // 128
#define SL_OFF   (SALPHA_OFF + 128)      // 128
#define SMEM_FLOATS (SL_OFF + 128)       // 25536 floats = 102144 bytes

__global__ __launch_bounds__(256) void attn_kernel(
    const float* __restrict__ biases, const int* __restrict__ idxs)
{
    extern __shared__ float smem[];
    float* sQ     = smem + SQ_OFF;
    float* sK     = smem + SK_OFF;
    float* sV     = smem + SV_OFF;
    float* sS     = smem + SS_OFF;
    float* sBias  = smem + SBIAS_OFF;
    float* sAlpha = smem + SALPHA_OFF;
    float* sL     = smem + SL_OFF;

    const int tid = threadIdx.x;
    const int h  = blockIdx.y;
    const int q0 = blockIdx.x * 128;

    // load Q tile (contiguous rows -> straight float4 copy)
    {
        const float4* src = (const float4*)(g_Q + (h * N_TOK + q0) * KD);
        float4* dst = (float4*)sQ;
        #pragma unroll
        for (int it = 0; it < 4; it++) dst[tid + it * 256] = src[tid + it * 256];
    }
    // load bias row for this head
    for (int i = tid; i < N_TOK; i += 256) sBias[i] = biases[h * N_TOK + i];

    // per-row softmax state (threads 0..127 own one row each)
    float m_r = -1e30f, l_r = 0.f;

    // O accumulators: thread (ty,tx) owns rows ty*8..+7, cols tx*8..+7
    const int ty = tid >> 4, tx = tid & 15;
    const int R = ty * 8, C8 = tx * 8, C4 = tx * 4;
    float accO[8][8];
    #pragma unroll
    for (int i = 0; i < 8; i++)
        #pragma unroll
        for (int j = 0; j < 8; j++) accO[i][j] = 0.f;

    __syncthreads();

    for (int k0 = 0; k0 < N_TOK; k0 += 64) {
        // --- load K tile (64x32, padded stride 33) ---
        {
            const float4* src = (const float4*)(g_K + (h * N_TOK + k0) * KD);
            #pragma unroll
            for (int it = 0; it < 2; it++) {
                int i = tid + it * 256;          // 0..511 float4s
                float4 kv = src[i];
                int c = i >> 3, kk = (i & 7) << 2;
                sK[c * 33 + kk + 0] = kv.x; sK[c * 33 + kk + 1] = kv.y;
                sK[c * 33 + kk + 2] = kv.z; sK[c * 33 + kk + 3] = kv.w;
            }
        }
        // --- load V tile (64x128, padded stride 132) ---
        {
            const float4* src = (const float4*)(g_V + (h * N_TOK + k0) * DV);
            #pragma unroll
            for (int it = 0; it < 8; it++) {
                int i = tid + it * 256;          // 0..2047 float4s
                float4 vv = src[i];
                int c = i >> 5, d = (i & 31) << 2;
                *(float4*)&sV[c * 132 + d] = vv;
            }
        }
        __syncthreads();

        // --- S = Q @ K^T : thread computes 8 rows x 4 cols ---
        {
            float s[8][4];
            #pragma unroll
            for (int i = 0; i < 8; i++)
                #pragma unroll
                for (int j = 0; j < 4; j++) s[i][j] = 0.f;
            #pragma unroll
            for (int k = 0; k < 32; k++) {
                float qv[8], kv[4];
                #pragma unroll
                for (int i = 0; i < 8; i++) qv[i] = sQ[(R + i) * 32 + k];
                #pragma unroll
                for (int j = 0; j < 4; j++) kv[j] = sK[(C4 + j) * 33 + k];
                #pragma unroll
                for (int i = 0; i < 8; i++)
                    #pragma unroll
                    for (int j = 0; j < 4; j++) s[i][j] += qv[i] * kv[j];
            }
            // scale + bias gather + stash to smem
            #pragma unroll
            for (int i = 0; i < 8; i++) {
                int n = q0 + R + i;
                int4 id4 = *(const int4*)(idxs + (long)n * N_TOK + k0 + C4);
                int ids[4] = {id4.x, id4.y, id4.z, id4.w};
                #pragma unroll
                for (int j = 0; j < 4; j++)
                    sS[(R + i) * 65 + C4 + j] = s[i][j] * SCALE_F + sBias[ids[j]];
            }
        }
        __syncthreads();

        // --- online softmax: thread tid<128 owns row tid ---
        if (tid < 128) {
            float mx = m_r;
            #pragma unroll 8
            for (int c = 0; c < 64; c++) mx = fmaxf(mx, sS[tid * 65 + c]);
            float alpha = __expf(m_r - mx);
            float sum = 0.f;
            #pragma unroll 8
            for (int c = 0; c < 64; c++) {
                float p = __expf(sS[tid * 65 + c] - mx);
                sS[tid * 65 + c] = p;
                sum += p;
            }
            l_r = l_r * alpha + sum;
            m_r = mx;
            sAlpha[tid] = alpha;
        }
        __syncthreads();

        // --- O = alpha*O + P @ V : thread owns 8x8 tile ---
        {
            float al[8];
            #pragma unroll
            for (int i = 0; i < 8; i++) al[i] = sAlpha[R + i];
            #pragma unroll
            for (int i = 0; i < 8; i++)
                #pragma unroll
                for (int j = 0; j < 8; j++) accO[i][j] *= al[i];
            for (int c2 = 0; c2 < 64; c2++) {
                float p[8];
                #pragma unroll
                for (int i = 0; i < 8; i++) p[i] = sS[(R + i) * 65 + c2];
                float4 v0 = *(const float4*)&sV[c2 * 132 + C8];
                float4 v1 = *(const float4*)&sV[c2 * 132 + C8 + 4];
                float vv[8] = {v0.x, v0.y, v0.z, v0.w, v1.x, v1.y, v1.z, v1.w};
                #pragma unroll
                for (int i = 0; i < 8; i++)
                    #pragma unroll
                    for (int j = 0; j < 8; j++) accO[i][j] += p[i] * vv[j];
            }
        }
        __syncthreads();
    }

    // finalize: divide by l, write O
    if (tid < 128) sL[tid] = l_r;
    __syncthreads();
    #pragma unroll
    for (int i = 0; i < 8; i++) {
        float inv = 1.f / sL[R + i];
        float4 o0, o1;
        o0.x = accO[i][0] * inv; o0.y = accO[i][1] * inv;
        o0.z = accO[i][2] * inv; o0.w = accO[i][3] * inv;
        o1.x = accO[i][4] * inv; o1.y = accO[i][5] * inv;
        o1.z = accO[i][6] * inv; o1.w = accO[i][7] * inv;
        float* dst = g_O + (long)(q0 + R + i) * DH + h * DV + C8;
        *(float4*)dst = o0;
        *(float4*)(dst + 4) = o1;
    }
}

// ---------------------------------------------------------------------------
// Kernel 3: output projection.  y = O @ proj_w^T + proj_b  (2304 x 384, K=1024)
// ---------------------------------------------------------------------------
__global__ __launch_bounds__(256) void proj_kernel(
    const float* __restrict__ Wp, const float* __restrict__ pb,
    float* __restrict__ out)
{
    __shared__ float sA[16][64];
    __shared__ float sB[16][64];

    const int tid = threadIdx.x;
    const int ty = tid >> 4, tx = tid & 15;
    const int rowBase = blockIdx.x * 64;
    const int colBase = blockIdx.y * 64;

    float acc[4][4];
    #pragma unroll
    for (int i = 0; i < 4; i++)
        #pragma unroll
        for (int j = 0; j < 4; j++) acc[i][j] = 0.f;

    const int lr = tid >> 2;
    const int lk = (tid & 3) << 2;

    for (int k0 = 0; k0 < DH; k0 += 16) {
        float4 a = *(const float4*)(g_O + (long)(rowBase + lr) * DH + k0 + lk);
        sA[lk + 0][lr] = a.x; sA[lk + 1][lr] = a.y;
        sA[lk + 2][lr] = a.z; sA[lk + 3][lr] = a.w;
        float4 b = *(const float4*)(Wp + (long)(colBase + lr) * DH + k0 + lk);
        sB[lk + 0][lr] = b.x; sB[lk + 1][lr] = b.y;
        sB[lk + 2][lr] = b.z; sB[lk + 3][lr] = b.w;
        __syncthreads();
        #pragma unroll
        for (int kk = 0; kk < 16; kk++) {
            float4 ra = *(const float4*)&sA[kk][ty * 4];
            float4 rb = *(const float4*)&sB[kk][tx * 4];
            float av[4] = {ra.x, ra.y, ra.z, ra.w};
            float bv[4] = {rb.x, rb.y, rb.z, rb.w};
            #pragma unroll
            for (int i = 0; i < 4; i++)
                #pragma unroll
                for (int j = 0; j < 4; j++) acc[i][j] += av[i] * bv[j];
        }
        __syncthreads();
    }

    #pragma unroll
    for (int i = 0; i < 4; i++) {
        int n = rowBase + ty * 4 + i;
        #pragma unroll
        for (int j = 0; j < 4; j++) {
            int o = colBase + tx * 4 + j;
            out[n * DIMX + o] = acc[i][j] + pb[o];
        }
    }
}

// ---------------------------------------------------------------------------
extern "C" void kernel_launch(void* const* d_in, const int* in_sizes, int n_in,
                              void* d_out, int out_size)
{
    const float* x       = (const float*)d_in[0];
    const float* q_w     = (const float*)d_in[1];
    const float* q_b     = (const float*)d_in[2];
    const float* k_w     = (const float*)d_in[3];
    const float* k_b     = (const float*)d_in[4];
    const float* v_w     = (const float*)d_in[5];
    const float* v_b     = (const float*)d_in[6];
    const float* proj_w  = (const float*)d_in[7];
    const float* proj_b  = (const float*)d_in[8];
    const float* biases  = (const float*)d_in[9];
    const int*   idxs    = (const int*)d_in[10];
    float* out = (float*)d_out;

    // 1) QKV projection: 2304 x 1536 output tiles of 64x64
    qkv_kernel<<<dim3(N_TOK / 64, 1536 / 64), 256>>>(x, q_w, q_b, k_w, k_b, v_w, v_b);

    // 2) attention
    const size_t smemBytes = SMEM_FLOATS * sizeof(float);
    cudaFuncSetAttribute(attn_kernel, cudaFuncAttributeMaxDynamicSharedMemorySize,
                         (int)smemBytes);
    attn_kernel<<<dim3(N_TOK / 128, NHEADS), 256, smemBytes>>>(biases, idxs);

    // 3) projection: 2304 x 384, K = 1024
    proj_kernel<<<dim3(N_TOK / 64, DIMX / 64), 256>>>(proj_w, proj_b, out);
}

// round 2
// speedup vs baseline: 2.7041x; 2.7041x over previous
#include <cuda_runtime.h>
#include <cstdint>

#define N_TOK 2304
#define DIMX 384
#define NHEADS 8
#define KD 32
#define DV 128
#define DH 1024
#define SCALE_F 0.17677669529663687f

// Scratch (allocation-free rule: __device__ globals)
__device__ float g_Q[NHEADS * N_TOK * KD];   // [h][n][32]
__device__ float g_K[NHEADS * N_TOK * KD];   // [h][n][32]
__device__ float g_V[NHEADS * N_TOK * DV];   // [h][n][128]
__device__ float g_O[N_TOK * DH];            // [n][h*128+d]

// ---------------------------------------------------------------------------
// helpers
// ---------------------------------------------------------------------------
__device__ __forceinline__ uint32_t f2tf(float f) {
    uint32_t u;
    asm("cvt.rna.tf32.f32 %0, %1;" : "=r"(u) : "f"(f));
    return u;
}

__device__ __forceinline__ void mma8(float* d,
                                     uint32_t a0, uint32_t a1, uint32_t a2, uint32_t a3,
                                     uint32_t b0, uint32_t b1)
{
    asm volatile(
        "mma.sync.aligned.m16n8k8.row.col.f32.tf32.tf32.f32 "
        "{%0,%1,%2,%3}, {%4,%5,%6,%7}, {%8,%9}, {%0,%1,%2,%3};\n"
        : "+f"(d[0]), "+f"(d[1]), "+f"(d[2]), "+f"(d[3])
        : "r"(a0), "r"(a1), "r"(a2), "r"(a3), "r"(b0), "r"(b1));
}

// ---------------------------------------------------------------------------
// Kernel 1: fused QKV projection. C = x @ W^T + b  (2304 x 1536, K=384)
// Block 128x64, Ktile 32, 8 warps (warp tile 32x32), tf32 mma.
// ---------------------------------------------------------------------------
__global__ __launch_bounds__(256) void qkv_mma(
    const float* __restrict__ x,
    const float* __restrict__ q_w, const float* __restrict__ q_b,
    const float* __restrict__ k_w, const float* __restrict__ k_b,
    const float* __restrict__ v_w, const float* __restrict__ v_b)
{
    __shared__ __align__(16) uint32_t sA[128 * 36];
    __shared__ __align__(16) uint32_t sB[64 * 36];

    const int tid  = threadIdx.x;
    const int warp = tid >> 5, lane = tid & 31;
    const int g = lane >> 2, t = lane & 3;
    const int warpM = warp & 3;   // 4 warps along M (32 rows each)
    const int warpN = warp >> 2;  // 2 warps along N (32 cols each)
    const int rowBase = blockIdx.x * 128;
    const int colBase = blockIdx.y * 64;

    const float* W; const float* bias; int sel, wBase;
    if (colBase < 256)      { W = q_w; bias = q_b; sel = 0; wBase = colBase;       }
    else if (colBase < 512) { W = k_w; bias = k_b; sel = 1; wBase = colBase - 256; }
    else                    { W = v_w; bias = v_b; sel = 2; wBase = colBase - 512; }

    float acc[2][4][4];
    #pragma unroll
    for (int mt = 0; mt < 2; mt++)
        #pragma unroll
        for (int nt = 0; nt < 4; nt++)
            #pragma unroll
            for (int j = 0; j < 4; j++) acc[mt][nt][j] = 0.f;

    for (int k0 = 0; k0 < DIMX; k0 += 32) {
        // load A: 128x32 floats (4 float4 per thread)
        #pragma unroll
        for (int it = 0; it < 4; it++) {
            int i = tid + it * 256;
            int r = i >> 3, c = (i & 7) << 2;
            float4 a = *(const float4*)(x + (rowBase + r) * DIMX + k0 + c);
            uint4 u = {f2tf(a.x), f2tf(a.y), f2tf(a.z), f2tf(a.w)};
            *(uint4*)&sA[r * 36 + c] = u;
        }
        // load B: 64x32 floats (2 float4 per thread)
        #pragma unroll
        for (int it = 0; it < 2; it++) {
            int i = tid + it * 256;
            int r = i >> 3, c = (i & 7) << 2;
            float4 b = *(const float4*)(W + (wBase + r) * DIMX + k0 + c);
            uint4 u = {f2tf(b.x), f2tf(b.y), f2tf(b.z), f2tf(b.w)};
            *(uint4*)&sB[r * 36 + c] = u;
        }
        __syncthreads();

        #pragma unroll
        for (int kk = 0; kk < 4; kk++) {
            uint32_t af[2][4], bf[4][2];
            #pragma unroll
            for (int mt = 0; mt < 2; mt++) {
                int row = warpM * 32 + mt * 16;
                af[mt][0] = sA[(row + g) * 36 + kk * 8 + t];
                af[mt][1] = sA[(row + 8 + g) * 36 + kk * 8 + t];
                af[mt][2] = sA[(row + g) * 36 + kk * 8 + t + 4];
                af[mt][3] = sA[(row + 8 + g) * 36 + kk * 8 + t + 4];
            }
            #pragma unroll
            for (int nt = 0; nt < 4; nt++) {
                int col = warpN * 32 + nt * 8;
                bf[nt][0] = sB[(col + g) * 36 + kk * 8 + t];
                bf[nt][1] = sB[(col + g) * 36 + kk * 8 + t + 4];
            }
            #pragma unroll
            for (int mt = 0; mt < 2; mt++)
                #pragma unroll
                for (int nt = 0; nt < 4; nt++)
                    mma8(acc[mt][nt], af[mt][0], af[mt][1], af[mt][2], af[mt][3],
                         bf[nt][0], bf[nt][1]);
        }
        __syncthreads();
    }

    // epilogue: bias + scatter into per-head layouts (float2 stores)
    #pragma unroll
    for (int nt = 0; nt < 4; nt++) {
        int jl = wBase + warpN * 32 + nt * 8 + 2 * t;  // col within selected weight
        float b0v = bias[jl], b1v = bias[jl + 1];
        #pragma unroll
        for (int mt = 0; mt < 2; mt++) {
            int row0 = rowBase + warpM * 32 + mt * 16 + g;
            int row1 = row0 + 8;
            float2 lo = {acc[mt][nt][0] + b0v, acc[mt][nt][1] + b1v};
            float2 hi = {acc[mt][nt][2] + b0v, acc[mt][nt][3] + b1v};
            if (sel == 0) {
                int h = jl >> 5, kd = jl & 31;
                *(float2*)&g_Q[(h * N_TOK + row0) * KD + kd] = lo;
                *(float2*)&g_Q[(h * N_TOK + row1) * KD + kd] = hi;
            } else if (sel == 1) {
                int h = jl >> 5, kd = jl & 31;
                *(float2*)&g_K[(h * N_TOK + row0) * KD + kd] = lo;
                *(float2*)&g_K[(h * N_TOK + row1) * KD + kd] = hi;
            } else {
                int h = jl >> 7, dv = jl & 127;
                *(float2*)&g_V[(h * N_TOK + row0) * DV + dv] = lo;
                *(float2*)&g_V[(h * N_TOK + row1) * DV + dv] = hi;
            }
        }
    }
}

// ---------------------------------------------------------------------------
// Kernel 2: flash attention, tf32 mma. BQ=128, BK=64, 8 warps.
// Warp w owns query rows 16w..16w+15 -> warp-local softmax.
// ---------------------------------------------------------------------------
#define AT_SQ    0                      // 128*36 = 4608
#define AT_SK    (AT_SQ + 128 * 36)     // 64*36  = 2304
#define AT_SV    (AT_SK + 64 * 36)      // 64*136 = 8704
#define AT_SS    (AT_SV + 64 * 136)     // 128*68 = 8704
#define AT_SBIAS (AT_SS + 128 * 68)     // 2304
#define AT_TOTAL (AT_SBIAS + N_TOK)     // 26624 u32 = 106496 bytes

__global__ __launch_bounds__(256, 1) void attn_mma(
    const float* __restrict__ biases, const int* __restrict__ idxs)
{
    extern __shared__ __align__(16) uint32_t smu[];
    uint32_t* sQ = smu + AT_SQ;
    uint32_t* sK = smu + AT_SK;
    uint32_t* sV = smu + AT_SV;
    uint32_t* sS = smu + AT_SS;
    float*    sBias = (float*)(smu + AT_SBIAS);

    const int tid  = threadIdx.x;
    const int warp = tid >> 5, lane = tid & 31;
    const int g = lane >> 2, t = lane & 3;
    const int h  = blockIdx.y;
    const int q0 = blockIdx.x * 128;

    // --- prologue: Q tile -> smem (tf32), bias row -> smem ---
    {
        const float4* src = (const float4*)(g_Q + (h * N_TOK + q0) * KD);
        #pragma unroll
        for (int it = 0; it < 4; it++) {
            int i = tid + it * 256;
            int r = i >> 3, c = (i & 7) << 2;
            float4 q = src[i];
            uint4 u = {f2tf(q.x), f2tf(q.y), f2tf(q.z), f2tf(q.w)};
            *(uint4*)&sQ[r * 36 + c] = u;
        }
        #pragma unroll
        for (int it = 0; it < 9; it++)
            sBias[tid + it * 256] = biases[h * N_TOK + tid + it * 256];
    }
    __syncthreads();

    // --- Q fragments, register resident: qf[kstep][4] ---
    uint32_t qf[4][4];
    {
        int row = 16 * warp + g;
        #pragma unroll
        for (int kk = 0; kk < 4; kk++) {
            qf[kk][0] = sQ[row * 36 + kk * 8 + t];
            qf[kk][1] = sQ[(row + 8) * 36 + kk * 8 + t];
            qf[kk][2] = sQ[row * 36 + kk * 8 + t + 4];
            qf[kk][3] = sQ[(row + 8) * 36 + kk * 8 + t + 4];
        }
    }

    float m0 = -1e30f, m1 = -1e30f, l0 = 0.f, l1 = 0.f;
    float o[16][4];
    #pragma unroll
    for (int vt = 0; vt < 16; vt++)
        #pragma unroll
        for (int j = 0; j < 4; j++) o[vt][j] = 0.f;

    const int rowW = 16 * warp + g;           // this thread's row0 within tile
    const int gRow0 = q0 + rowW;              // global query row 0
    const int gRow1 = gRow0 + 8;              // global query row 1

    for (int k0 = 0; k0 < N_TOK; k0 += 64) {
        __syncthreads();   // previous iteration's sK/sV fully consumed
        // --- load K tile 64x32 (stride 36) ---
        {
            const float4* src = (const float4*)(g_K + (h * N_TOK + k0) * KD);
            #pragma unroll
            for (int it = 0; it < 2; it++) {
                int i = tid + it * 256;
                int r = i >> 3, c = (i & 7) << 2;
                float4 k = src[i];
                uint4 u = {f2tf(k.x), f2tf(k.y), f2tf(k.z), f2tf(k.w)};
                *(uint4*)&sK[r * 36 + c] = u;
            }
        }
        // --- load V tile 64x128 (stride 136) ---
        {
            const float4* src = (const float4*)(g_V + (h * N_TOK + k0) * DV);
            #pragma unroll
            for (int it = 0; it < 8; it++) {
                int i = tid + it * 256;
                int r = i >> 5, c = (i & 31) << 2;
                float4 v = src[i];
                uint4 u = {f2tf(v.x), f2tf(v.y), f2tf(v.z), f2tf(v.w)};
                *(uint4*)&sV[r * 136 + c] = u;
            }
        }
        __syncthreads();

        // --- S = Q @ K^T (warp rows x 64) + scale + bias gather ---
        float sreg[8][4];
        #pragma unroll
        for (int nt = 0; nt < 8; nt++) {
            float s4[4] = {0.f, 0.f, 0.f, 0.f};
            #pragma unroll
            for (int kk = 0; kk < 4; kk++) {
                uint32_t b0 = sK[(nt * 8 + g) * 36 + kk * 8 + t];
                uint32_t b1 = sK[(nt * 8 + g) * 36 + kk * 8 + t + 4];
                mma8(s4, qf[kk][0], qf[kk][1], qf[kk][2], qf[kk][3], b0, b1);
            }
            int colg = k0 + nt * 8 + 2 * t;
            int2 id0 = *(const int2*)(idxs + (long)gRow0 * N_TOK + colg);
            int2 id1 = *(const int2*)(idxs + (long)gRow1 * N_TOK + colg);
            sreg[nt][0] = s4[0] * SCALE_F + sBias[id0.x];
            sreg[nt][1] = s4[1] * SCALE_F + sBias[id0.y];
            sreg[nt][2] = s4[2] * SCALE_F + sBias[id1.x];
            sreg[nt][3] = s4[3] * SCALE_F + sBias[id1.y];
        }

        // --- online softmax, warp-local (quad reduction) ---
        float mx0 = m0, mx1 = m1;
        #pragma unroll
        for (int nt = 0; nt < 8; nt++) {
            mx0 = fmaxf(mx0, fmaxf(sreg[nt][0], sreg[nt][1]));
            mx1 = fmaxf(mx1, fmaxf(sreg[nt][2], sreg[nt][3]));
        }
        mx0 = fmaxf(mx0, __shfl_xor_sync(0xffffffffu, mx0, 1));
        mx0 = fmaxf(mx0, __shfl_xor_sync(0xffffffffu, mx0, 2));
        mx1 = fmaxf(mx1, __shfl_xor_sync(0xffffffffu, mx1, 1));
        mx1 = fmaxf(mx1, __shfl_xor_sync(0xffffffffu, mx1, 2));
        float a0 = __expf(m0 - mx0), a1 = __expf(m1 - mx1);
        float sum0 = 0.f, sum1 = 0.f;
        #pragma unroll
        for (int nt = 0; nt < 8; nt++) {
            float p0 = __expf(sreg[nt][0] - mx0);
            float p1 = __expf(sreg[nt][1] - mx0);
            float p2 = __expf(sreg[nt][2] - mx1);
            float p3 = __expf(sreg[nt][3] - mx1);
            sum0 += p0 + p1; sum1 += p2 + p3;
            // store P (tf32) to per-warp sS region
            uint2 u0 = {f2tf(p0), f2tf(p1)};
            uint2 u1 = {f2tf(p2), f2tf(p3)};
            *(uint2*)&sS[rowW * 68 + nt * 8 + 2 * t] = u0;
            *(uint2*)&sS[(rowW + 8) * 68 + nt * 8 + 2 * t] = u1;
        }
        sum0 += __shfl_xor_sync(0xffffffffu, sum0, 1);
        sum0 += __shfl_xor_sync(0xffffffffu, sum0, 2);
        sum1 += __shfl_xor_sync(0xffffffffu, sum1, 1);
        sum1 += __shfl_xor_sync(0xffffffffu, sum1, 2);
        l0 = l0 * a0 + sum0; m0 = mx0;
        l1 = l1 * a1 + sum1; m1 = mx1;

        // rescale O
        #pragma unroll
        for (int vt = 0; vt < 16; vt++) {
            o[vt][0] *= a0; o[vt][1] *= a0;
            o[vt][2] *= a1; o[vt][3] *= a1;
        }
        __syncwarp();

        // --- O += P @ V ---
        #pragma unroll
        for (int kk = 0; kk < 8; kk++) {
            uint32_t p0 = sS[rowW * 68 + kk * 8 + t];
            uint32_t p1 = sS[(rowW + 8) * 68 + kk * 8 + t];
            uint32_t p2 = sS[rowW * 68 + kk * 8 + t + 4];
            uint32_t p3 = sS[(rowW + 8) * 68 + kk * 8 + t + 4];
            #pragma unroll
            for (int vt = 0; vt < 16; vt++) {
                uint32_t b0 = sV[(kk * 8 + t) * 136 + vt * 8 + g];
                uint32_t b1 = sV[(kk * 8 + t + 4) * 136 + vt * 8 + g];
                mma8(o[vt], p0, p1, p2, p3, b0, b1);
            }
        }
    }

    // --- finalize, write O ---
    float inv0 = 1.f / l0, inv1 = 1.f / l1;
    #pragma unroll
    for (int vt = 0; vt < 16; vt++) {
        int col = vt * 8 + 2 * t;
        float2 lo = {o[vt][0] * inv0, o[vt][1] * inv0};
        float2 hi = {o[vt][2] * inv1, o[vt][3] * inv1};
        *(float2*)&g_O[(long)gRow0 * DH + h * DV + col] = lo;
        *(float2*)&g_O[(long)gRow1 * DH + h * DV + col] = hi;
    }
}

// ---------------------------------------------------------------------------
// Kernel 3: output projection. y = O @ proj_w^T + proj_b (2304 x 384, K=1024)
// ---------------------------------------------------------------------------
__global__ __launch_bounds__(256) void proj_mma(
    const float* __restrict__ Wp, const float* __restrict__ pb,
    float* __restrict__ out)
{
    __shared__ __align__(16) uint32_t sA[128 * 36];
    __shared__ __align__(16) uint32_t sB[64 * 36];

    const int tid  = threadIdx.x;
    const int warp = tid >> 5, lane = tid & 31;
    const int g = lane >> 2, t = lane & 3;
    const int warpM = warp & 3;
    const int warpN = warp >> 2;
    const int rowBase = blockIdx.x * 128;
    const int colBase = blockIdx.y * 64;

    float acc[2][4][4];
    #pragma unroll
    for (int mt = 0; mt < 2; mt++)
        #pragma unroll
        for (int nt = 0; nt < 4; nt++)
            #pragma unroll
            for (int j = 0; j < 4; j++) acc[mt][nt][j] = 0.f;

    for (int k0 = 0; k0 < DH; k0 += 32) {
        #pragma unroll
        for (int it = 0; it < 4; it++) {
            int i = tid + it * 256;
            int r = i >> 3, c = (i & 7) << 2;
            float4 a = *(const float4*)(g_O + (long)(rowBase + r) * DH + k0 + c);
            uint4 u = {f2tf(a.x), f2tf(a.y), f2tf(a.z), f2tf(a.w)};
            *(uint4*)&sA[r * 36 + c] = u;
        }
        #pragma unroll
        for (int it = 0; it < 2; it++) {
            int i = tid + it * 256;
            int r = i >> 3, c = (i & 7) << 2;
            float4 b = *(const float4*)(Wp + (long)(colBase + r) * DH + k0 + c);
            uint4 u = {f2tf(b.x), f2tf(b.y), f2tf(b.z), f2tf(b.w)};
            *(uint4*)&sB[r * 36 + c] = u;
        }
        __syncthreads();

        #pragma unroll
        for (int kk = 0; kk < 4; kk++) {
            uint32_t af[2][4], bf[4][2];
            #pragma unroll
            for (int mt = 0; mt < 2; mt++) {
                int row = warpM * 32 + mt * 16;
                af[mt][0] = sA[(row + g) * 36 + kk * 8 + t];
                af[mt][1] = sA[(row + 8 + g) * 36 + kk * 8 + t];
                af[mt][2] = sA[(row + g) * 36 + kk * 8 + t + 4];
                af[mt][3] = sA[(row + 8 + g) * 36 + kk * 8 + t + 4];
            }
            #pragma unroll
            for (int nt = 0; nt < 4; nt++) {
                int col = warpN * 32 + nt * 8;
                bf[nt][0] = sB[(col + g) * 36 + kk * 8 + t];
                bf[nt][1] = sB[(col + g) * 36 + kk * 8 + t + 4];
            }
            #pragma unroll
            for (int mt = 0; mt < 2; mt++)
                #pragma unroll
                for (int nt = 0; nt < 4; nt++)
                    mma8(acc[mt][nt], af[mt][0], af[mt][1], af[mt][2], af[mt][3],
                         bf[nt][0], bf[nt][1]);
        }
        __syncthreads();
    }

    #pragma unroll
    for (int nt = 0; nt < 4; nt++) {
        int col = colBase + warpN * 32 + nt * 8 + 2 * t;
        float b0v = pb[col], b1v = pb[col + 1];
        #pragma unroll
        for (int mt = 0; mt < 2; mt++) {
            int row0 = rowBase + warpM * 32 + mt * 16 + g;
            int row1 = row0 + 8;
            float2 lo = {acc[mt][nt][0] + b0v, acc[mt][nt][1] + b1v};
            float2 hi = {acc[mt][nt][2] + b0v, acc[mt][nt][3] + b1v};
            *(float2*)&out[row0 * DIMX + col] = lo;
            *(float2*)&out[row1 * DIMX + col] = hi;
        }
    }
}

// ---------------------------------------------------------------------------
extern "C" void kernel_launch(void* const* d_in, const int* in_sizes, int n_in,
                              void* d_out, int out_size)
{
    const float* x       = (const float*)d_in[0];
    const float* q_w     = (const float*)d_in[1];
    const float* q_b     = (const float*)d_in[2];
    const float* k_w     = (const float*)d_in[3];
    const float* k_b     = (const float*)d_in[4];
    const float* v_w     = (const float*)d_in[5];
    const float* v_b     = (const float*)d_in[6];
    const float* proj_w  = (const float*)d_in[7];
    const float* proj_b  = (const float*)d_in[8];
    const float* biases  = (const float*)d_in[9];
    const int*   idxs    = (const int*)d_in[10];
    float* out = (float*)d_out;

    qkv_mma<<<dim3(N_TOK / 128, 1536 / 64), 256>>>(x, q_w, q_b, k_w, k_b, v_w, v_b);

    const size_t smemBytes = AT_TOTAL * sizeof(uint32_t);
    cudaFuncSetAttribute(attn_mma, cudaFuncAttributeMaxDynamicSharedMemorySize,
                         (int)smemBytes);
    attn_mma<<<dim3(N_TOK / 128, NHEADS), 256, smemBytes>>>(biases, idxs);

    proj_mma<<<dim3(N_TOK / 128, DIMX / 64), 256>>>(proj_w, proj_b, out);
}